// round 8
// baseline (speedup 1.0000x reference)
#include <cuda_runtime.h>
#include <cuda_bf16.h>

#define NN 100000
#define EE 3200000
#define DD 16
#define EPSV 1e-5f
#define DEGB 256
#define NGROUP 12500                 // NN/8 groups of 8 equal-degree nodes
#define PERM_CAP (EE + 2000000)      // padded warp-tiled capacity

// ---- static device scratch (allocation-free rule) ----
__device__ int      g_counts[NN];
__device__ int      g_cursor[NN];
__device__ int      g_wbase[NN];       // per-node write base (record index)
__device__ int      g_deghist[DEGB];
__device__ int      g_degcur[DEGB];
__device__ int      g_sorted[NN];      // degree-sorted node ids
__device__ int      g_groupmax[NGROUP];
__device__ int      g_tilebase[NGROUP];
__device__ int4     g_nodeinfo[NN];    // {node, start, end, 0}; stride-8 walk
__device__ int2     g_perm[PERM_CAP];  // warp-tiled {src, bitcast(w)}
__device__ float    g_bufA[NN * DD];
__device__ float    g_bufB[NN * DD];

// ---------------- build ----------------

__global__ void zero_kernel() {
    int i = blockIdx.x * blockDim.x + threadIdx.x;
    if (i < NN) { g_counts[i] = 0; g_cursor[i] = 0; }
    if (i < NGROUP) g_groupmax[i] = 0;
    if (i < DEGB) g_deghist[i] = 0;
}

// 4 edges per thread via int4 (EE divisible by 4)
__global__ void hist_kernel(const int4* __restrict__ dst4) {
    int i = blockIdx.x * blockDim.x + threadIdx.x;
    if (i < EE / 4) {
        int4 d = dst4[i];
        atomicAdd(&g_counts[d.x], 1);
        atomicAdd(&g_counts[d.y], 1);
        atomicAdd(&g_counts[d.z], 1);
        atomicAdd(&g_counts[d.w], 1);
    }
}

__global__ void deghist_kernel() {
    int i = blockIdx.x * blockDim.x + threadIdx.x;
    if (i < NN) {
        int deg = g_counts[i];
        atomicAdd(&g_deghist[deg < DEGB ? deg : DEGB - 1], 1);
    }
}

__global__ void degscan_kernel() {
    __shared__ int sh[DEGB];
    int tid = threadIdx.x;
    int v = g_deghist[tid];
    sh[tid] = v;
    __syncthreads();
    for (int off = 1; off < DEGB; off <<= 1) {
        int t = (tid >= off) ? sh[tid - off] : 0;
        __syncthreads();
        sh[tid] += t;
        __syncthreads();
    }
    g_degcur[tid] = sh[tid] - v;
}

// degree-sorted placement + per-group max degree
__global__ void order_kernel() {
    int i = blockIdx.x * blockDim.x + threadIdx.x;
    if (i < NN) {
        int deg = g_counts[i];
        int bin = deg < DEGB ? deg : DEGB - 1;
        int pos = atomicAdd(&g_degcur[bin], 1);
        g_sorted[pos] = i;
        atomicMax(&g_groupmax[pos >> 3], deg);
    }
}

// exclusive scan of 8*groupmax over 12500 groups (single block, 13 chunks)
__global__ void tilescan_kernel() {
    __shared__ int sh[1024];
    __shared__ int s_carry;
    int tid = threadIdx.x;
    if (tid == 0) s_carry = 0;
    __syncthreads();
    for (int base = 0; base < NGROUP; base += 1024) {
        int i = base + tid;
        int v = (i < NGROUP) ? 8 * g_groupmax[i] : 0;
        sh[tid] = v;
        __syncthreads();
        for (int off = 1; off < 1024; off <<= 1) {
            int t = (tid >= off) ? sh[tid - off] : 0;
            __syncthreads();
            sh[tid] += t;
            __syncthreads();
        }
        if (i < NGROUP) g_tilebase[i] = sh[tid] - v + s_carry;
        __syncthreads();
        if (tid == 1023) s_carry += sh[1023];
        __syncthreads();
    }
}

// node write-bases, warp-tiled nodeinfo, and zero-weight pad records
__global__ void finalize_kernel() {
    int i = blockIdx.x * blockDim.x + threadIdx.x;
    if (i < NN) {
        int node = g_sorted[i];
        int g    = i & 7;
        int grp  = i >> 3;
        int base = g_tilebase[grp];
        int maxd = g_groupmax[grp];
        int deg  = g_counts[node];
        int start = base + g;
        g_wbase[node] = start;
        g_nodeinfo[i] = make_int4(node, start, start + 8 * maxd, 0);
        for (int t = deg; t < maxd; ++t) {
            int2 p; p.x = node; p.y = 0;      // exact 0.0f weight -> contributes 0
            g_perm[start + 8 * t] = p;
        }
    }
}

// 4 edges per thread; pos = wbase[dst] + t*8 (warp-tiled layout)
__global__ void scatter_kernel(const int4* __restrict__ src4,
                               const int4* __restrict__ dst4,
                               const float4* __restrict__ attr4) {
    int i = blockIdx.x * blockDim.x + threadIdx.x;
    if (i < EE / 4) {
        int4   s = src4[i];
        int4   d = dst4[i];
        float4 a = attr4[i];
        int p0 = g_wbase[d.x] + atomicAdd(&g_cursor[d.x], 1) * 8;
        int p1 = g_wbase[d.y] + atomicAdd(&g_cursor[d.y], 1) * 8;
        int p2 = g_wbase[d.z] + atomicAdd(&g_cursor[d.z], 1) * 8;
        int p3 = g_wbase[d.w] + atomicAdd(&g_cursor[d.w], 1) * 8;
        int2 r0; r0.x = s.x; r0.y = __float_as_int(sqrtf(a.x));
        int2 r1; r1.x = s.y; r1.y = __float_as_int(sqrtf(a.y));
        int2 r2; r2.x = s.z; r2.y = __float_as_int(sqrtf(a.z));
        int2 r3; r3.x = s.w; r3.y = __float_as_int(sqrtf(a.w));
        g_perm[p0] = r0;
        g_perm[p1] = r1;
        g_perm[p2] = r2;
        g_perm[p3] = r3;
    }
}

// ---------------- iteration ----------------
// 4 lanes per node; lane l owns dims [4l, 4l+4).  256 thr = 64 nodes/block.
// Warp-tiled perm: trip t of the warp's 8 groups reads 64B contiguous.
__global__ __launch_bounds__(256) void iterate_kernel(
        const float4* __restrict__ sin,
        const float4* __restrict__ x0v,
        float4* __restrict__ sout) {
    int idx  = blockIdx.x * 64 + (threadIdx.x >> 2);
    int lane = threadIdx.x & 3;
    if (idx >= NN) return;

    int4 info = g_nodeinfo[idx];
    int node  = info.x;
    float4 xi = sin[node * 4 + lane];

    float4 num = make_float4(0.f, 0.f, 0.f, 0.f);
    float4 den = make_float4(0.f, 0.f, 0.f, 0.f);

    #pragma unroll 2
    for (int e = info.y; e < info.z; e += 8) {
        int2 rec  = g_perm[e];                 // warp reads 64B contiguous/trip
        float we  = __int_as_float(rec.y);
        float4 xj = sin[rec.x * 4 + lane];     // coalesced 64B gather per group

        float w0 = __fdividef(we, fabsf(xj.x - xi.x + EPSV));
        float w1 = __fdividef(we, fabsf(xj.y - xi.y + EPSV));
        float w2 = __fdividef(we, fabsf(xj.z - xi.z + EPSV));
        float w3 = __fdividef(we, fabsf(xj.w - xi.w + EPSV));
        num.x += w0 * xj.x;  den.x += w0;
        num.y += w1 * xj.y;  den.y += w1;
        num.z += w2 * xj.z;  den.z += w2;
        num.w += w3 * xj.w;  den.w += w3;
    }

    float4 x0n = x0v[node * 4 + lane];
    float4 r;
    r.x = __fdividef(x0n.x + num.x, 1.0f + den.x);
    r.y = __fdividef(x0n.y + num.y, 1.0f + den.y);
    r.z = __fdividef(x0n.z + num.z, 1.0f + den.z);
    r.w = __fdividef(x0n.w + num.w, 1.0f + den.w);
    sout[node * 4 + lane] = r;
}

// ---------------- launch ----------------

extern "C" void kernel_launch(void* const* d_in, const int* in_sizes, int n_in,
                              void* d_out, int out_size) {
    const float* signal     = (const float*)d_in[0];
    const float* x0         = (const float*)d_in[1];
    const float* edge_attr  = (const float*)d_in[2];
    const int*   edge_index = (const int*)  d_in[3];
    float* out = (float*)d_out;

    float *bufA, *bufB;
    cudaGetSymbolAddress((void**)&bufA, g_bufA);
    cudaGetSymbolAddress((void**)&bufB, g_bufB);

    // build: counts -> degree sort -> warp tiles -> scatter (once per launch)
    zero_kernel<<<(NN + 255) / 256, 256>>>();
    hist_kernel<<<(EE / 4 + 255) / 256, 256>>>((const int4*)(edge_index + EE));
    deghist_kernel<<<(NN + 255) / 256, 256>>>();
    degscan_kernel<<<1, DEGB>>>();
    order_kernel<<<(NN + 255) / 256, 256>>>();
    tilescan_kernel<<<1, 1024>>>();
    finalize_kernel<<<(NN + 255) / 256, 256>>>();
    scatter_kernel<<<(EE / 4 + 255) / 256, 256>>>(
        (const int4*)edge_index,
        (const int4*)(edge_index + EE),
        (const float4*)edge_attr);

    int grid = (NN + 63) / 64;
    const float4* x0v = (const float4*)x0;

    // itr = 5: signal -> A -> B -> A -> B -> out
    iterate_kernel<<<grid, 256>>>((const float4*)signal, x0v, (float4*)bufA);
    iterate_kernel<<<grid, 256>>>((const float4*)bufA,   x0v, (float4*)bufB);
    iterate_kernel<<<grid, 256>>>((const float4*)bufB,   x0v, (float4*)bufA);
    iterate_kernel<<<grid, 256>>>((const float4*)bufA,   x0v, (float4*)bufB);
    iterate_kernel<<<grid, 256>>>((const float4*)bufB,   x0v, (float4*)out);
}

// round 9
// speedup vs baseline: 1.0408x; 1.0408x over previous
#include <cuda_runtime.h>
#include <cuda_bf16.h>

#define NN 100000
#define EE 3200000
#define DD 16
#define EPSV 1e-5f
#define NB 98              // ceil(NN/1024)
#define DEGB 256
#define HALF_N 50000

// ---- static device scratch (allocation-free rule) ----
__device__ int      g_counts[NN];
__device__ int      g_offsets[NN + 1];
__device__ int      g_cursor[NN];
__device__ int      g_blocksums[128];
__device__ int      g_deghist[DEGB];
__device__ int      g_degcur[DEGB];
__device__ int4     g_nodeinfo[NN];     // {node, start, end, pad}, degree-sorted
__device__ int2     g_perm[EE];         // {src, bitcast(sqrt(edge_attr))} — exact
__device__ float    g_bufA[NN * DD];
__device__ float    g_bufB[NN * DD];

// ---------------- build ----------------

__global__ void zero_kernel() {
    int i = blockIdx.x * blockDim.x + threadIdx.x;
    if (i < NN) g_counts[i] = 0;
    if (i < DEGB) g_deghist[i] = 0;
}

// 4 edges per thread via int4 (EE divisible by 4)
__global__ void hist_kernel(const int4* __restrict__ dst4) {
    int i = blockIdx.x * blockDim.x + threadIdx.x;
    if (i < EE / 4) {
        int4 d = dst4[i];
        atomicAdd(&g_counts[d.x], 1);
        atomicAdd(&g_counts[d.y], 1);
        atomicAdd(&g_counts[d.z], 1);
        atomicAdd(&g_counts[d.w], 1);
    }
}

// hierarchical scan of g_counts -> g_offsets (exclusive)
__global__ void scan1_kernel() {
    __shared__ int sh[1024];
    int b = blockIdx.x, tid = threadIdx.x;
    int i = b * 1024 + tid;
    int v = (i < NN) ? g_counts[i] : 0;
    sh[tid] = v;
    __syncthreads();
    for (int off = 1; off < 1024; off <<= 1) {
        int t = (tid >= off) ? sh[tid - off] : 0;
        __syncthreads();
        sh[tid] += t;
        __syncthreads();
    }
    if (i < NN) g_offsets[i] = sh[tid] - v;    // block-local exclusive
    if (tid == 1023) g_blocksums[b] = sh[1023];
}

__global__ void scan2_kernel() {
    __shared__ int sh[128];
    int tid = threadIdx.x;
    int v = (tid < NB) ? g_blocksums[tid] : 0;
    sh[tid] = v;
    __syncthreads();
    for (int off = 1; off < 128; off <<= 1) {
        int t = (tid >= off) ? sh[tid - off] : 0;
        __syncthreads();
        sh[tid] += t;
        __syncthreads();
    }
    if (tid < NB) g_blocksums[tid] = sh[tid] - v;  // exclusive block bases
    if (tid == 127) g_offsets[NN] = sh[127];       // grand total (== EE)
}

// fixup + cursor init + degree histogram (fused)
__global__ void scan3_kernel() {
    int i = blockIdx.x * blockDim.x + threadIdx.x;
    if (i < NN) {
        int o = g_offsets[i] + g_blocksums[i >> 10];
        g_offsets[i] = o;
        g_cursor[i]  = o;
        int deg = g_counts[i];
        atomicAdd(&g_deghist[deg < DEGB ? deg : DEGB - 1], 1);
    }
}

__global__ void degscan_kernel() {
    __shared__ int sh[DEGB];
    int tid = threadIdx.x;
    int v = g_deghist[tid];
    sh[tid] = v;
    __syncthreads();
    for (int off = 1; off < DEGB; off <<= 1) {
        int t = (tid >= off) ? sh[tid - off] : 0;
        __syncthreads();
        sh[tid] += t;
        __syncthreads();
    }
    g_degcur[tid] = sh[tid] - v;
}

// degree-sorted node records so each warp gets 8 equal-degree nodes
__global__ void order_kernel() {
    int i = blockIdx.x * blockDim.x + threadIdx.x;
    if (i < NN) {
        int deg = g_counts[i];
        int bin = deg < DEGB ? deg : DEGB - 1;
        int pos = atomicAdd(&g_degcur[bin], 1);
        int start = g_offsets[i];
        g_nodeinfo[pos] = make_int4(i, start, start + deg, 0);
    }
}

// 4 edges per thread: 4 independent atomic+store chains in flight
__global__ void scatter_kernel(const int4* __restrict__ src4,
                               const int4* __restrict__ dst4,
                               const float4* __restrict__ attr4) {
    int i = blockIdx.x * blockDim.x + threadIdx.x;
    if (i < EE / 4) {
        int4   s = src4[i];
        int4   d = dst4[i];
        float4 a = attr4[i];
        int p0 = atomicAdd(&g_cursor[d.x], 1);
        int p1 = atomicAdd(&g_cursor[d.y], 1);
        int p2 = atomicAdd(&g_cursor[d.z], 1);
        int p3 = atomicAdd(&g_cursor[d.w], 1);
        int2 r0; r0.x = s.x; r0.y = __float_as_int(sqrtf(a.x));
        int2 r1; r1.x = s.y; r1.y = __float_as_int(sqrtf(a.y));
        int2 r2; r2.x = s.z; r2.y = __float_as_int(sqrtf(a.z));
        int2 r3; r3.x = s.w; r3.y = __float_as_int(sqrtf(a.w));
        g_perm[p0] = r0;
        g_perm[p1] = r1;
        g_perm[p2] = r2;
        g_perm[p3] = r3;
    }
}

// ---------------- iteration ----------------
// 4 lanes per node; lane l owns dims [4l, 4l+4).
// Each thread-group handles TWO nodes sequentially (idx and idx+HALF_N):
// grid halves to 200K threads -> single SM wave, no partial-wave tail.
__global__ __launch_bounds__(256) void iterate_kernel(
        const float4* __restrict__ sin,
        const float4* __restrict__ x0v,
        float4* __restrict__ sout) {
    int base = blockIdx.x * 64 + (threadIdx.x >> 2);
    int lane = threadIdx.x & 3;
    if (base >= HALF_N) return;

    #pragma unroll 1
    for (int h = 0; h < 2; ++h) {
        int idx = base + h * HALF_N;

        int4 info = g_nodeinfo[idx];
        int node  = info.x;
        float4 xi = sin[node * 4 + lane];

        float4 num = make_float4(0.f, 0.f, 0.f, 0.f);
        float4 den = make_float4(0.f, 0.f, 0.f, 0.f);

        #pragma unroll 2
        for (int e = info.y; e < info.z; ++e) {
            int2 rec  = g_perm[e];                 // broadcast across the 4 lanes
            float we  = __int_as_float(rec.y);
            float4 xj = sin[rec.x * 4 + lane];     // coalesced 64B gather per group

            float w0 = __fdividef(we, fabsf(xj.x - xi.x + EPSV));
            float w1 = __fdividef(we, fabsf(xj.y - xi.y + EPSV));
            float w2 = __fdividef(we, fabsf(xj.z - xi.z + EPSV));
            float w3 = __fdividef(we, fabsf(xj.w - xi.w + EPSV));
            num.x += w0 * xj.x;  den.x += w0;
            num.y += w1 * xj.y;  den.y += w1;
            num.z += w2 * xj.z;  den.z += w2;
            num.w += w3 * xj.w;  den.w += w3;
        }

        float4 x0n = x0v[node * 4 + lane];
        float4 r;
        r.x = __fdividef(x0n.x + num.x, 1.0f + den.x);
        r.y = __fdividef(x0n.y + num.y, 1.0f + den.y);
        r.z = __fdividef(x0n.z + num.z, 1.0f + den.z);
        r.w = __fdividef(x0n.w + num.w, 1.0f + den.w);
        sout[node * 4 + lane] = r;
    }
}

// ---------------- launch ----------------

extern "C" void kernel_launch(void* const* d_in, const int* in_sizes, int n_in,
                              void* d_out, int out_size) {
    const float* signal     = (const float*)d_in[0];
    const float* x0         = (const float*)d_in[1];
    const float* edge_attr  = (const float*)d_in[2];
    const int*   edge_index = (const int*)  d_in[3];
    float* out = (float*)d_out;

    float *bufA, *bufB;
    cudaGetSymbolAddress((void**)&bufA, g_bufA);
    cudaGetSymbolAddress((void**)&bufB, g_bufB);

    // CSR build + degree-balanced ordering (once per launch)
    zero_kernel<<<(NN + 255) / 256, 256>>>();
    hist_kernel<<<(EE / 4 + 255) / 256, 256>>>((const int4*)(edge_index + EE));
    scan1_kernel<<<NB, 1024>>>();
    scan2_kernel<<<1, 128>>>();
    scan3_kernel<<<(NN + 255) / 256, 256>>>();
    degscan_kernel<<<1, DEGB>>>();
    order_kernel<<<(NN + 255) / 256, 256>>>();
    scatter_kernel<<<(EE / 4 + 255) / 256, 256>>>(
        (const int4*)edge_index,
        (const int4*)(edge_index + EE),
        (const float4*)edge_attr);

    int grid = (HALF_N + 63) / 64;   // 782 blocks = 200K threads, single wave
    const float4* x0v = (const float4*)x0;

    // itr = 5: signal -> A -> B -> A -> B -> out
    iterate_kernel<<<grid, 256>>>((const float4*)signal, x0v, (float4*)bufA);
    iterate_kernel<<<grid, 256>>>((const float4*)bufA,   x0v, (float4*)bufB);
    iterate_kernel<<<grid, 256>>>((const float4*)bufB,   x0v, (float4*)bufA);
    iterate_kernel<<<grid, 256>>>((const float4*)bufA,   x0v, (float4*)bufB);
    iterate_kernel<<<grid, 256>>>((const float4*)bufB,   x0v, (float4*)out);
}

// round 10
// speedup vs baseline: 1.1305x; 1.0862x over previous
#include <cuda_runtime.h>
#include <cuda_bf16.h>

#define NN 100000
#define EE 3200000
#define DD 16
#define EPSV 1e-5f
#define NB 98              // ceil(NN/1024)
#define DEGB 256
#define NCHUNK 1563        // ceil(NN/64) 64-node chunks
#define PBLOCKS 1184       // 8 blocks/SM * 148 SMs

// ---- static device scratch (allocation-free rule) ----
__device__ int      g_counts[NN];
__device__ int      g_offsets[NN + 1];
__device__ int      g_cursor[NN];
__device__ int      g_blocksums[128];
__device__ int      g_deghist[DEGB];
__device__ int      g_degcur[DEGB];
__device__ int      g_tickets[8];       // one ticket counter per iteration
__device__ int4     g_nodeinfo[NN];     // {node, start, end, pad}, degree-sorted
__device__ int2     g_perm[EE];         // {src, bitcast(sqrt(edge_attr))} — exact
__device__ float    g_bufA[NN * DD];
__device__ float    g_bufB[NN * DD];

// ---------------- build ----------------

__global__ void zero_kernel() {
    int i = blockIdx.x * blockDim.x + threadIdx.x;
    if (i < NN) g_counts[i] = 0;
    if (i < DEGB) g_deghist[i] = 0;
    if (i < 8) g_tickets[i] = 0;
}

// 4 edges per thread via int4 (EE divisible by 4)
__global__ void hist_kernel(const int4* __restrict__ dst4) {
    int i = blockIdx.x * blockDim.x + threadIdx.x;
    if (i < EE / 4) {
        int4 d = dst4[i];
        atomicAdd(&g_counts[d.x], 1);
        atomicAdd(&g_counts[d.y], 1);
        atomicAdd(&g_counts[d.z], 1);
        atomicAdd(&g_counts[d.w], 1);
    }
}

// hierarchical scan of g_counts -> g_offsets (exclusive)
__global__ void scan1_kernel() {
    __shared__ int sh[1024];
    int b = blockIdx.x, tid = threadIdx.x;
    int i = b * 1024 + tid;
    int v = (i < NN) ? g_counts[i] : 0;
    sh[tid] = v;
    __syncthreads();
    for (int off = 1; off < 1024; off <<= 1) {
        int t = (tid >= off) ? sh[tid - off] : 0;
        __syncthreads();
        sh[tid] += t;
        __syncthreads();
    }
    if (i < NN) g_offsets[i] = sh[tid] - v;    // block-local exclusive
    if (tid == 1023) g_blocksums[b] = sh[1023];
}

__global__ void scan2_kernel() {
    __shared__ int sh[128];
    int tid = threadIdx.x;
    int v = (tid < NB) ? g_blocksums[tid] : 0;
    sh[tid] = v;
    __syncthreads();
    for (int off = 1; off < 128; off <<= 1) {
        int t = (tid >= off) ? sh[tid - off] : 0;
        __syncthreads();
        sh[tid] += t;
        __syncthreads();
    }
    if (tid < NB) g_blocksums[tid] = sh[tid] - v;  // exclusive block bases
    if (tid == 127) g_offsets[NN] = sh[127];       // grand total (== EE)
}

// fixup + cursor init + degree histogram (fused)
__global__ void scan3_kernel() {
    int i = blockIdx.x * blockDim.x + threadIdx.x;
    if (i < NN) {
        int o = g_offsets[i] + g_blocksums[i >> 10];
        g_offsets[i] = o;
        g_cursor[i]  = o;
        int deg = g_counts[i];
        atomicAdd(&g_deghist[deg < DEGB ? deg : DEGB - 1], 1);
    }
}

__global__ void degscan_kernel() {
    __shared__ int sh[DEGB];
    int tid = threadIdx.x;
    int v = g_deghist[tid];
    sh[tid] = v;
    __syncthreads();
    for (int off = 1; off < DEGB; off <<= 1) {
        int t = (tid >= off) ? sh[tid - off] : 0;
        __syncthreads();
        sh[tid] += t;
        __syncthreads();
    }
    g_degcur[tid] = sh[tid] - v;
}

// degree-sorted node records so each warp gets 8 equal-degree nodes
__global__ void order_kernel() {
    int i = blockIdx.x * blockDim.x + threadIdx.x;
    if (i < NN) {
        int deg = g_counts[i];
        int bin = deg < DEGB ? deg : DEGB - 1;
        int pos = atomicAdd(&g_degcur[bin], 1);
        int start = g_offsets[i];
        g_nodeinfo[pos] = make_int4(i, start, start + deg, 0);
    }
}

// 4 edges per thread: 4 independent atomic+store chains in flight
__global__ void scatter_kernel(const int4* __restrict__ src4,
                               const int4* __restrict__ dst4,
                               const float4* __restrict__ attr4) {
    int i = blockIdx.x * blockDim.x + threadIdx.x;
    if (i < EE / 4) {
        int4   s = src4[i];
        int4   d = dst4[i];
        float4 a = attr4[i];
        int p0 = atomicAdd(&g_cursor[d.x], 1);
        int p1 = atomicAdd(&g_cursor[d.y], 1);
        int p2 = atomicAdd(&g_cursor[d.z], 1);
        int p3 = atomicAdd(&g_cursor[d.w], 1);
        int2 r0; r0.x = s.x; r0.y = __float_as_int(sqrtf(a.x));
        int2 r1; r1.x = s.y; r1.y = __float_as_int(sqrtf(a.y));
        int2 r2; r2.x = s.z; r2.y = __float_as_int(sqrtf(a.z));
        int2 r3; r3.x = s.w; r3.y = __float_as_int(sqrtf(a.w));
        g_perm[p0] = r0;
        g_perm[p1] = r1;
        g_perm[p2] = r2;
        g_perm[p3] = r3;
    }
}

// ---------------- iteration ----------------
// Persistent blocks + dynamic 64-node chunk tickets (descending degree = LPT).
// 4 lanes per node; lane l owns dims [4l, 4l+4).  256 thr = 64 nodes/chunk.
__global__ __launch_bounds__(256) void iterate_kernel(
        const float4* __restrict__ sin,
        const float4* __restrict__ x0v,
        float4* __restrict__ sout,
        int it) {
    __shared__ int s_chunk;
    int tid  = threadIdx.x;
    int lane = tid & 3;
    int slot = tid >> 2;

    while (true) {
        if (tid == 0) s_chunk = atomicAdd(&g_tickets[it], 1);
        __syncthreads();
        int c = s_chunk;
        __syncthreads();
        if (c >= NCHUNK) break;
        c = NCHUNK - 1 - c;                  // largest-degree chunks first (LPT)

        int idx = c * 64 + slot;
        if (idx < NN) {
            int4 info = g_nodeinfo[idx];
            int node  = info.x;
            float4 xi = sin[node * 4 + lane];

            float4 num = make_float4(0.f, 0.f, 0.f, 0.f);
            float4 den = make_float4(0.f, 0.f, 0.f, 0.f);

            #pragma unroll 2
            for (int e = info.y; e < info.z; ++e) {
                int2 rec  = g_perm[e];             // broadcast across the 4 lanes
                float we  = __int_as_float(rec.y);
                float4 xj = sin[rec.x * 4 + lane]; // coalesced 64B gather/group

                float w0 = __fdividef(we, fabsf(xj.x - xi.x + EPSV));
                float w1 = __fdividef(we, fabsf(xj.y - xi.y + EPSV));
                float w2 = __fdividef(we, fabsf(xj.z - xi.z + EPSV));
                float w3 = __fdividef(we, fabsf(xj.w - xi.w + EPSV));
                num.x += w0 * xj.x;  den.x += w0;
                num.y += w1 * xj.y;  den.y += w1;
                num.z += w2 * xj.z;  den.z += w2;
                num.w += w3 * xj.w;  den.w += w3;
            }

            float4 x0n = x0v[node * 4 + lane];
            float4 r;
            r.x = __fdividef(x0n.x + num.x, 1.0f + den.x);
            r.y = __fdividef(x0n.y + num.y, 1.0f + den.y);
            r.z = __fdividef(x0n.z + num.z, 1.0f + den.z);
            r.w = __fdividef(x0n.w + num.w, 1.0f + den.w);
            sout[node * 4 + lane] = r;
        }
    }
}

// ---------------- launch ----------------

extern "C" void kernel_launch(void* const* d_in, const int* in_sizes, int n_in,
                              void* d_out, int out_size) {
    const float* signal     = (const float*)d_in[0];
    const float* x0         = (const float*)d_in[1];
    const float* edge_attr  = (const float*)d_in[2];
    const int*   edge_index = (const int*)  d_in[3];
    float* out = (float*)d_out;

    float *bufA, *bufB;
    cudaGetSymbolAddress((void**)&bufA, g_bufA);
    cudaGetSymbolAddress((void**)&bufB, g_bufB);

    // CSR build + degree-balanced ordering (once per launch)
    zero_kernel<<<(NN + 255) / 256, 256>>>();
    hist_kernel<<<(EE / 4 + 255) / 256, 256>>>((const int4*)(edge_index + EE));
    scan1_kernel<<<NB, 1024>>>();
    scan2_kernel<<<1, 128>>>();
    scan3_kernel<<<(NN + 255) / 256, 256>>>();
    degscan_kernel<<<1, DEGB>>>();
    order_kernel<<<(NN + 255) / 256, 256>>>();
    scatter_kernel<<<(EE / 4 + 255) / 256, 256>>>(
        (const int4*)edge_index,
        (const int4*)(edge_index + EE),
        (const float4*)edge_attr);

    const float4* x0v = (const float4*)x0;

    // itr = 5: signal -> A -> B -> A -> B -> out  (persistent, ticket-scheduled)
    iterate_kernel<<<PBLOCKS, 256>>>((const float4*)signal, x0v, (float4*)bufA, 0);
    iterate_kernel<<<PBLOCKS, 256>>>((const float4*)bufA,   x0v, (float4*)bufB, 1);
    iterate_kernel<<<PBLOCKS, 256>>>((const float4*)bufB,   x0v, (float4*)bufA, 2);
    iterate_kernel<<<PBLOCKS, 256>>>((const float4*)bufA,   x0v, (float4*)bufB, 3);
    iterate_kernel<<<PBLOCKS, 256>>>((const float4*)bufB,   x0v, (float4*)out,  4);
}

// round 11
// speedup vs baseline: 1.2224x; 1.0813x over previous
#include <cuda_runtime.h>
#include <cuda_bf16.h>

#define NN 100000
#define EE 3200000
#define DD 16
#define EPSV 1e-5f
#define DEGB 256
#define MAXDEG 128           // Poisson(32): P(deg>=96) ~ 1e-19; 128 is safe
#define NCHUNK 1563          // ceil(NN/64) 64-node chunks
#define PBLOCKS 1184         // 8 blocks/SM * 148 SMs

// ---- static device scratch (allocation-free rule) ----
__device__ int      g_cursor[NN];          // per-node fill cursor == final degree
__device__ int      g_deghist[DEGB];
__device__ int      g_degcur[DEGB];
__device__ int      g_tickets[8];          // one ticket counter per iteration
__device__ int4     g_nodeinfo[NN];        // {node, start, end, 0}, degree-sorted
__device__ int2     g_perm[NN * MAXDEG];   // fixed 128-record slot per node
__device__ float    g_bufA[NN * DD];
__device__ float    g_bufB[NN * DD];

// ---------------- build ----------------

__global__ void zero_kernel() {
    int i = blockIdx.x * blockDim.x + threadIdx.x;
    if (i < NN) g_cursor[i] = 0;
    if (i < DEGB) g_deghist[i] = 0;
    if (i < 8) g_tickets[i] = 0;
}

// 4 edges per thread; slot-addressed scatter (no offsets needed)
__global__ void scatter_kernel(const int4* __restrict__ src4,
                               const int4* __restrict__ dst4,
                               const float4* __restrict__ attr4) {
    int i = blockIdx.x * blockDim.x + threadIdx.x;
    if (i < EE / 4) {
        int4   s = src4[i];
        int4   d = dst4[i];
        float4 a = attr4[i];
        int p0 = atomicAdd(&g_cursor[d.x], 1);
        int p1 = atomicAdd(&g_cursor[d.y], 1);
        int p2 = atomicAdd(&g_cursor[d.z], 1);
        int p3 = atomicAdd(&g_cursor[d.w], 1);
        int2 r0; r0.x = s.x; r0.y = __float_as_int(sqrtf(a.x));
        int2 r1; r1.x = s.y; r1.y = __float_as_int(sqrtf(a.y));
        int2 r2; r2.x = s.z; r2.y = __float_as_int(sqrtf(a.z));
        int2 r3; r3.x = s.w; r3.y = __float_as_int(sqrtf(a.w));
        g_perm[d.x * MAXDEG + p0] = r0;
        g_perm[d.y * MAXDEG + p1] = r1;
        g_perm[d.z * MAXDEG + p2] = r2;
        g_perm[d.w * MAXDEG + p3] = r3;
    }
}

__global__ void deghist_kernel() {
    int i = blockIdx.x * blockDim.x + threadIdx.x;
    if (i < NN) {
        int deg = g_cursor[i];               // cursor == final degree
        atomicAdd(&g_deghist[deg < DEGB ? deg : DEGB - 1], 1);
    }
}

__global__ void degscan_kernel() {
    __shared__ int sh[DEGB];
    int tid = threadIdx.x;
    int v = g_deghist[tid];
    sh[tid] = v;
    __syncthreads();
    for (int off = 1; off < DEGB; off <<= 1) {
        int t = (tid >= off) ? sh[tid - off] : 0;
        __syncthreads();
        sh[tid] += t;
        __syncthreads();
    }
    g_degcur[tid] = sh[tid] - v;
}

// degree-sorted node records so each warp gets 8 equal-degree nodes
__global__ void order_kernel() {
    int i = blockIdx.x * blockDim.x + threadIdx.x;
    if (i < NN) {
        int deg = g_cursor[i];
        int bin = deg < DEGB ? deg : DEGB - 1;
        int pos = atomicAdd(&g_degcur[bin], 1);
        int start = i * MAXDEG;
        g_nodeinfo[pos] = make_int4(i, start, start + deg, 0);
    }
}

// ---------------- iteration ----------------
// Persistent blocks + dynamic 64-node chunk tickets (descending degree = LPT).
// 4 lanes per node; lane l owns dims [4l, 4l+4).  256 thr = 64 nodes/chunk.
__global__ __launch_bounds__(256) void iterate_kernel(
        const float4* __restrict__ sin,
        const float4* __restrict__ x0v,
        float4* __restrict__ sout,
        int it) {
    __shared__ int s_chunk;
    int tid  = threadIdx.x;
    int lane = tid & 3;
    int slot = tid >> 2;

    while (true) {
        if (tid == 0) s_chunk = atomicAdd(&g_tickets[it], 1);
        __syncthreads();
        int c = s_chunk;
        __syncthreads();
        if (c >= NCHUNK) break;
        c = NCHUNK - 1 - c;                  // largest-degree chunks first (LPT)

        int idx = c * 64 + slot;
        if (idx < NN) {
            int4 info = g_nodeinfo[idx];
            int node  = info.x;
            float4 xi = sin[node * 4 + lane];

            float4 num = make_float4(0.f, 0.f, 0.f, 0.f);
            float4 den = make_float4(0.f, 0.f, 0.f, 0.f);

            #pragma unroll 2
            for (int e = info.y; e < info.z; ++e) {
                int2 rec  = g_perm[e];             // broadcast across the 4 lanes
                float we  = __int_as_float(rec.y);
                float4 xj = sin[rec.x * 4 + lane]; // coalesced 64B gather/group

                float w0 = __fdividef(we, fabsf(xj.x - xi.x + EPSV));
                float w1 = __fdividef(we, fabsf(xj.y - xi.y + EPSV));
                float w2 = __fdividef(we, fabsf(xj.z - xi.z + EPSV));
                float w3 = __fdividef(we, fabsf(xj.w - xi.w + EPSV));
                num.x += w0 * xj.x;  den.x += w0;
                num.y += w1 * xj.y;  den.y += w1;
                num.z += w2 * xj.z;  den.z += w2;
                num.w += w3 * xj.w;  den.w += w3;
            }

            float4 x0n = x0v[node * 4 + lane];
            float4 r;
            r.x = __fdividef(x0n.x + num.x, 1.0f + den.x);
            r.y = __fdividef(x0n.y + num.y, 1.0f + den.y);
            r.z = __fdividef(x0n.z + num.z, 1.0f + den.z);
            r.w = __fdividef(x0n.w + num.w, 1.0f + den.w);
            sout[node * 4 + lane] = r;
        }
    }
}

// ---------------- launch ----------------

extern "C" void kernel_launch(void* const* d_in, const int* in_sizes, int n_in,
                              void* d_out, int out_size) {
    const float* signal     = (const float*)d_in[0];
    const float* x0         = (const float*)d_in[1];
    const float* edge_attr  = (const float*)d_in[2];
    const int*   edge_index = (const int*)  d_in[3];
    float* out = (float*)d_out;

    float *bufA, *bufB;
    cudaGetSymbolAddress((void**)&bufA, g_bufA);
    cudaGetSymbolAddress((void**)&bufB, g_bufB);

    // build: slot scatter + degree-balanced ordering (5 kernels)
    zero_kernel<<<(NN + 255) / 256, 256>>>();
    scatter_kernel<<<(EE / 4 + 255) / 256, 256>>>(
        (const int4*)edge_index,
        (const int4*)(edge_index + EE),
        (const float4*)edge_attr);
    deghist_kernel<<<(NN + 255) / 256, 256>>>();
    degscan_kernel<<<1, DEGB>>>();
    order_kernel<<<(NN + 255) / 256, 256>>>();

    const float4* x0v = (const float4*)x0;

    // itr = 5: signal -> A -> B -> A -> B -> out  (persistent, ticket-scheduled)
    iterate_kernel<<<PBLOCKS, 256>>>((const float4*)signal, x0v, (float4*)bufA, 0);
    iterate_kernel<<<PBLOCKS, 256>>>((const float4*)bufA,   x0v, (float4*)bufB, 1);
    iterate_kernel<<<PBLOCKS, 256>>>((const float4*)bufB,   x0v, (float4*)bufA, 2);
    iterate_kernel<<<PBLOCKS, 256>>>((const float4*)bufA,   x0v, (float4*)bufB, 3);
    iterate_kernel<<<PBLOCKS, 256>>>((const float4*)bufB,   x0v, (float4*)out,  4);
}

// round 12
// speedup vs baseline: 1.2307x; 1.0068x over previous
#include <cuda_runtime.h>
#include <cuda_bf16.h>

#define NN 100000
#define EE 3200000
#define DD 16
#define EPSV 1e-5f
#define DEGB 256
#define MAXDEG 128           // Poisson(32): P(deg>=96) ~ 1e-19; 128 is safe
#define NCHUNK 1563          // ceil(NN/64) 64-node chunks
#define PBLOCKS 1184         // 8 blocks/SM * 148 SMs
#define SORTBLK 148          // 1 block/SM -> co-residency guaranteed

// ---- static device scratch (allocation-free rule) ----
__device__ int      g_cursor[NN];          // per-node fill cursor == final degree
__device__ int      g_deghist[DEGB];
__device__ int      g_degcur[DEGB];        // claim counters (start at 0)
__device__ int      g_tickets[8];          // per-iteration ticket counters
__device__ int      g_bar;                 // software grid barrier arrive count
__device__ int4     g_nodeinfo[NN];        // {node, start, end, 0}, degree-sorted
__device__ int2     g_perm[NN * MAXDEG];   // fixed 128-record slot per node
__device__ float    g_bufA[NN * DD];
__device__ float    g_bufB[NN * DD];

// ---------------- build ----------------

__global__ void zero_kernel() {
    int i = blockIdx.x * blockDim.x + threadIdx.x;
    if (i < NN) g_cursor[i] = 0;
    if (i < DEGB) { g_deghist[i] = 0; g_degcur[i] = 0; }
    if (i < 8) g_tickets[i] = 0;
    if (i == 8) g_bar = 0;
}

// 4 edges per thread; slot-addressed scatter (no offsets needed)
__global__ void scatter_kernel(const int4* __restrict__ src4,
                               const int4* __restrict__ dst4,
                               const float4* __restrict__ attr4) {
    int i = blockIdx.x * blockDim.x + threadIdx.x;
    if (i < EE / 4) {
        int4   s = src4[i];
        int4   d = dst4[i];
        float4 a = attr4[i];
        int p0 = atomicAdd(&g_cursor[d.x], 1);
        int p1 = atomicAdd(&g_cursor[d.y], 1);
        int p2 = atomicAdd(&g_cursor[d.z], 1);
        int p3 = atomicAdd(&g_cursor[d.w], 1);
        int2 r0; r0.x = s.x; r0.y = __float_as_int(sqrtf(a.x));
        int2 r1; r1.x = s.y; r1.y = __float_as_int(sqrtf(a.y));
        int2 r2; r2.x = s.z; r2.y = __float_as_int(sqrtf(a.z));
        int2 r3; r3.x = s.w; r3.y = __float_as_int(sqrtf(a.w));
        g_perm[d.x * MAXDEG + p0] = r0;
        g_perm[d.y * MAXDEG + p1] = r1;
        g_perm[d.z * MAXDEG + p2] = r2;
        g_perm[d.w * MAXDEG + p3] = r3;
    }
}

// fused deghist + scan + order: 148 co-resident blocks, one software barrier
__global__ __launch_bounds__(256) void buildsort_kernel() {
    __shared__ int sh[DEGB];
    int tid = threadIdx.x;
    int gid = blockIdx.x * blockDim.x + tid;
    int stride = SORTBLK * 256;

    // Phase A: degree histogram (grid-strided)
    for (int i = gid; i < NN; i += stride) {
        int deg = g_cursor[i];
        atomicAdd(&g_deghist[deg < DEGB ? deg : DEGB - 1], 1);
    }

    // software grid barrier (all SORTBLK blocks are co-resident at 1/SM)
    __threadfence();
    __syncthreads();
    if (tid == 0) {
        atomicAdd(&g_bar, 1);
        while (atomicAdd(&g_bar, 0) < SORTBLK) { }
    }
    __syncthreads();

    // Phase B: every block scans the 256-bin histogram locally (redundant,
    // cheaper than a second barrier), then claims positions per bin.
    int v = g_deghist[tid];
    sh[tid] = v;
    __syncthreads();
    for (int off = 1; off < DEGB; off <<= 1) {
        int t = (tid >= off) ? sh[tid - off] : 0;
        __syncthreads();
        sh[tid] += t;
        __syncthreads();
    }
    // sh[b] is inclusive; exclusive base of bin b = sh[b] - hist[b]
    __shared__ int base[DEGB];
    base[tid] = sh[tid] - v;
    __syncthreads();

    for (int i = gid; i < NN; i += stride) {
        int deg = g_cursor[i];
        int bin = deg < DEGB ? deg : DEGB - 1;
        int pos = base[bin] + atomicAdd(&g_degcur[bin], 1);
        int start = i * MAXDEG;
        g_nodeinfo[pos] = make_int4(i, start, start + deg, 0);
    }
}

// ---------------- iteration ----------------
// Persistent blocks + dynamic 64-node chunk tickets (descending degree = LPT).
// 4 lanes per node; lane l owns dims [4l, 4l+4).  256 thr = 64 nodes/chunk.
__global__ __launch_bounds__(256) void iterate_kernel(
        const float4* __restrict__ sin,
        const float4* __restrict__ x0v,
        float4* __restrict__ sout,
        int it) {
    __shared__ int s_chunk;
    int tid  = threadIdx.x;
    int lane = tid & 3;
    int slot = tid >> 2;

    while (true) {
        if (tid == 0) s_chunk = atomicAdd(&g_tickets[it], 1);
        __syncthreads();
        int c = s_chunk;
        __syncthreads();
        if (c >= NCHUNK) break;
        c = NCHUNK - 1 - c;                  // largest-degree chunks first (LPT)

        int idx = c * 64 + slot;
        if (idx < NN) {
            int4 info = g_nodeinfo[idx];
            int node  = info.x;
            float4 xi = sin[node * 4 + lane];

            float4 num = make_float4(0.f, 0.f, 0.f, 0.f);
            float4 den = make_float4(0.f, 0.f, 0.f, 0.f);

            #pragma unroll 2
            for (int e = info.y; e < info.z; ++e) {
                int2 rec  = g_perm[e];             // broadcast across the 4 lanes
                float we  = __int_as_float(rec.y);
                float4 xj = sin[rec.x * 4 + lane]; // coalesced 64B gather/group

                float w0 = __fdividef(we, fabsf(xj.x - xi.x + EPSV));
                float w1 = __fdividef(we, fabsf(xj.y - xi.y + EPSV));
                float w2 = __fdividef(we, fabsf(xj.z - xi.z + EPSV));
                float w3 = __fdividef(we, fabsf(xj.w - xi.w + EPSV));
                num.x += w0 * xj.x;  den.x += w0;
                num.y += w1 * xj.y;  den.y += w1;
                num.z += w2 * xj.z;  den.z += w2;
                num.w += w3 * xj.w;  den.w += w3;
            }

            float4 x0n = x0v[node * 4 + lane];
            float4 r;
            r.x = __fdividef(x0n.x + num.x, 1.0f + den.x);
            r.y = __fdividef(x0n.y + num.y, 1.0f + den.y);
            r.z = __fdividef(x0n.z + num.z, 1.0f + den.z);
            r.w = __fdividef(x0n.w + num.w, 1.0f + den.w);
            sout[node * 4 + lane] = r;
        }
    }
}

// ---------------- launch ----------------

extern "C" void kernel_launch(void* const* d_in, const int* in_sizes, int n_in,
                              void* d_out, int out_size) {
    const float* signal     = (const float*)d_in[0];
    const float* x0         = (const float*)d_in[1];
    const float* edge_attr  = (const float*)d_in[2];
    const int*   edge_index = (const int*)  d_in[3];
    float* out = (float*)d_out;

    float *bufA, *bufB;
    cudaGetSymbolAddress((void**)&bufA, g_bufA);
    cudaGetSymbolAddress((void**)&bufB, g_bufB);

    // build: zero + slot scatter + fused degree sort (3 kernels)
    zero_kernel<<<(NN + 255) / 256, 256>>>();
    scatter_kernel<<<(EE / 4 + 255) / 256, 256>>>(
        (const int4*)edge_index,
        (const int4*)(edge_index + EE),
        (const float4*)edge_attr);
    buildsort_kernel<<<SORTBLK, 256>>>();

    const float4* x0v = (const float4*)x0;

    // itr = 5: signal -> A -> B -> A -> B -> out  (persistent, ticket-scheduled)
    iterate_kernel<<<PBLOCKS, 256>>>((const float4*)signal, x0v, (float4*)bufA, 0);
    iterate_kernel<<<PBLOCKS, 256>>>((const float4*)bufA,   x0v, (float4*)bufB, 1);
    iterate_kernel<<<PBLOCKS, 256>>>((const float4*)bufB,   x0v, (float4*)bufA, 2);
    iterate_kernel<<<PBLOCKS, 256>>>((const float4*)bufA,   x0v, (float4*)bufB, 3);
    iterate_kernel<<<PBLOCKS, 256>>>((const float4*)bufB,   x0v, (float4*)out,  4);
}